// round 9
// baseline (speedup 1.0000x reference)
#include <cuda_runtime.h>

#define NQ      12
#define DIM     4096
#define THREADS 256
#define EPT     16
#define STSZ    4352        // max padded addr 4350
typedef unsigned long long ull;

#define SGN2  0x8000000080000000ULL   // packed fp32x2 sign-bit flip

__device__ __forceinline__ ull pk(float lo, float hi) {
    ull r; asm("mov.b64 %0, {%1, %2};" : "=l"(r) : "f"(lo), "f"(hi)); return r;
}
__device__ __forceinline__ void upk(ull a, float& lo, float& hi) {
    asm("mov.b64 {%0, %1}, %2;" : "=f"(lo), "=f"(hi) : "l"(a));
}
__device__ __forceinline__ ull fma2(ull a, ull b, ull c) {
    ull d; asm("fma.rn.f32x2 %0, %1, %2, %3;" : "=l"(d) : "l"(a), "l"(b), "l"(c)); return d;
}
__device__ __forceinline__ ull mul2(ull a, ull b) {
    ull d; asm("mul.rn.f32x2 %0, %1, %2;" : "=l"(d) : "l"(a), "l"(b)); return d;
}
__device__ __forceinline__ ull add2(ull a, ull b) {
    ull d; asm("add.rn.f32x2 %0, %1, %2;" : "=l"(d) : "l"(a), "l"(b)); return d;
}
__device__ __forceinline__ ull sub2(ull a, ull b) { return fma2(b, 0xBF800000BF800000ULL, a); }

// tan-form RY butterfly (deferred cosine): a0' = a0 - t*a1 ; a1' = a1 + t*a0
// exact gate = cos * (a0', a1'); cosines folded into final output scale.
#define REG_BF4T(TT, TNT, QBASE)                                           \
    _Pragma("unroll")                                                      \
    for (int rb = 0; rb < 4; rb++) {                                       \
        const ull t2  = (TT)[(QBASE) + rb];                                \
        const ull nt2 = (TNT)[(QBASE) + rb];                               \
        _Pragma("unroll")                                                  \
        for (int m = 0; m < 8; m++) {                                      \
            const int low = (1 << rb) - 1;                                 \
            const int j0  = ((m & ~low) << 1) | (m & low);                 \
            const int j1  = j0 | (1 << rb);                                \
            ull a0 = v[j0];                                                \
            v[j0] = fma2(nt2, v[j1], a0);                                  \
            v[j1] = fma2(t2,  a0,   v[j1]);                                \
        }                                                                  \
    }

__global__ __launch_bounds__(THREADS, 4)
void qc_kernel(const float* __restrict__ x,
               const float* __restrict__ th,
               float* __restrict__ out)
{
    __shared__ ull st2[STSZ];
    __shared__ ull enc_c[NQ], enc_s[NQ];
    __shared__ ull th_t[2][NQ], th_nt[2][NQ];
    __shared__ float cosv[2 * NQ];
    __shared__ ull red[(THREADS / 32) * NQ];

    const int b    = blockIdx.x;           // batch items 2b, 2b+1
    const int tid  = threadIdx.x;
    const int lane = tid & 31;

    // padded bases (8B elements; addr = s + (s>>4); conflict-free A/B/C)
    const int baseA = 17 * tid;                               // + j
    const int baseB = tid + (tid >> 4);                       // + 272*j
    const int tb    = ((tid >> 5) & 1) | (((tid >> 4) & 1) << 1)
                    | (((tid >> 6) & 1) << 2) | (((tid >> 7) & 1) << 3);
    const int baseC = (tid & 15) + 272 * tb;                  // + 17*j

    // ---- angle precompute ----
    if (tid < NQ) {
        float c0, s0, c1, s1;
        sincosf(0.5f * x[(2 * b) * NQ + tid],     &s0, &c0);
        sincosf(0.5f * x[(2 * b + 1) * NQ + tid], &s1, &c1);
        enc_c[tid] = pk(c0, c1);
        enc_s[tid] = pk(s0, s1);
    } else if (tid >= 32 && tid < 32 + 2 * NQ) {
        int k = tid - 32;                 // k = layer*12 + q
        int layer = k / NQ, q = k % NQ;
        float s_, c_;
        sincosf(0.5f * th[k], &s_, &c_);
        float t_ = s_ / c_;
        th_t[layer][q]  = pk(t_, t_);
        th_nt[layer][q] = pk(-t_, -t_);
        cosv[k] = c_;
    }
    __syncthreads();

    // ---- packed product state (ownership A: s = 16*tid + j) ----
    ull v[EPT];
    {
        ull h = (tid & 1) ? enc_s[4] : enc_c[4];
        #pragma unroll
        for (int i = 1; i < 8; i++)
            h = mul2(h, ((tid >> i) & 1) ? enc_s[4 + i] : enc_c[4 + i]);
        ull lo[4], hi[4];
        #pragma unroll
        for (int m = 0; m < 4; m++) {
            lo[m] = mul2((m & 1) ? enc_s[0] : enc_c[0], (m & 2) ? enc_s[1] : enc_c[1]);
            hi[m] = mul2((m & 1) ? enc_s[2] : enc_c[2], (m & 2) ? enc_s[3] : enc_c[3]);
        }
        #pragma unroll
        for (int j = 0; j < EPT; j++)
            v[j] = mul2(mul2(h, lo[j & 3]), hi[j >> 2]);
    }

    // ---- variational layers (tan-form gates, cosines deferred) ----
    #pragma unroll
    for (int layer = 0; layer < 2; layer++) {
        const ull* T  = th_t[layer];
        const ull* NT = th_nt[layer];

        REG_BF4T(T, NT, 0)                      // qubits 0-3 (A)

        #pragma unroll
        for (int j = 0; j < EPT; j++) st2[baseA + j] = v[j];
        __syncthreads();
        #pragma unroll
        for (int j = 0; j < EPT; j++) v[j] = st2[baseC + 17 * j];

        REG_BF4T(T, NT, 4)                      // qubits 4-7 (C)

        #pragma unroll
        for (int j = 0; j < EPT; j++) st2[baseC + 17 * j] = v[j];
        __syncthreads();
        #pragma unroll
        for (int j = 0; j < EPT; j++) v[j] = st2[baseB + 272 * j];

        REG_BF4T(T, NT, 8)                      // qubits 8-11 (B)

        if (layer == 0) {
            // CNOT ring = bit-linear permutation; scatter B -> gather A
            unsigned px = tid; px ^= px << 1; px ^= px << 2; px ^= px << 4;
            const int Pt  = (px >> 7) & 1;
            const int Tt  = (tid ^ (int)(px << 1)) & 0xFE;
            const int t0p = (tid & 1) ^ Pt;
            const int pb0 = Tt + t0p       + (Tt >> 4);
            const int pb1 = Tt + (t0p ^ 1) + (Tt >> 4);
            const int msk = Pt ? 15 : 0;

            __syncthreads();                    // all B reads done before scatter
            #pragma unroll
            for (int j = 0; j < EPT; j++) {
                const int j0 = j & 1, j1 = (j >> 1) & 1, j2 = (j >> 2) & 1, j3 = (j >> 3) & 1;
                const int Jv = j0 | ((j1 ^ j0) << 1) | ((j2 ^ j1 ^ j0) << 2)
                             | ((j3 ^ j2 ^ j1 ^ j0) << 3);
                const int pj = j0 ^ j1 ^ j2 ^ j3;
                st2[(pj ? pb1 : pb0) + 272 * (Jv ^ msk)] = v[j];
            }
            __syncthreads();
            #pragma unroll
            for (int j = 0; j < EPT; j++) v[j] = st2[baseA + j];
        }
        // layer 1: ring permutation folded into expectation signs
    }

    // ---- expectations (ownership B) via packed Walsh combine ----
    ull a[8], d[8];
    #pragma unroll
    for (int k = 0; k < 8; k++) {
        ull pe = mul2(v[2 * k],     v[2 * k]);
        ull po = mul2(v[2 * k + 1], v[2 * k + 1]);
        a[k] = add2(pe, po);
        d[k] = sub2(pe, po);
    }
    ull P  = add2(add2(add2(a[0], a[1]), add2(a[2], a[3])),
                  add2(add2(a[4], a[5]), add2(a[6], a[7])));
    ull e0 = add2(d[0], d[1]), e1 = add2(d[2], d[3]);
    ull e2 = add2(d[4], d[5]), e3 = add2(d[6], d[7]);
    ull f0 = sub2(d[0], d[1]), f1 = sub2(d[2], d[3]);
    ull f2 = sub2(d[4], d[5]), f3 = sub2(d[6], d[7]);
    ull g1 = add2(add2(e0, e1), add2(e2, e3));
    ull g3 = add2(add2(f0, f1), add2(f2, f3));
    ull g7 = add2(sub2(f0, f1), sub2(f2, f3));
    ull gF = sub2(add2(f0, f3), add2(f1, f2));

    const int pt  = __popc(tid) & 1;
    const int pt1 = __popc(tid >> 1) & 1;

    ull acc[NQ];
    acc[0] = pt1 ? (gF ^ SGN2) : gF;
    #pragma unroll
    for (int q = 1; q < 8; q++) {
        int sq = __popc(tid & ((1 << (q + 1)) - 1)) & 1;
        acc[q] = sq ? (P ^ SGN2) : P;
    }
    acc[8]  = pt ? (g1 ^ SGN2) : g1;
    acc[9]  = pt ? (g3 ^ SGN2) : g3;
    acc[10] = pt ? (g7 ^ SGN2) : g7;
    acc[11] = pt ? (gF ^ SGN2) : gF;

    #pragma unroll
    for (int q = 0; q < NQ; q++) {
        #pragma unroll
        for (int off = 16; off; off >>= 1)
            acc[q] = add2(acc[q], __shfl_down_sync(0xFFFFFFFFu, acc[q], off));
    }
    const int w = tid >> 5;
    if (lane == 0) {
        #pragma unroll
        for (int q = 0; q < NQ; q++) red[w * NQ + q] = acc[q];
    }
    __syncthreads();
    if (tid < NQ) {
        ull r = red[tid];
        #pragma unroll
        for (int w2 = 1; w2 < THREADS / 32; w2++) r = add2(r, red[w2 * NQ + tid]);
        // deferred cosine scale: out *= (prod_{24 gates} cos)^2
        float cs = cosv[0];
        #pragma unroll
        for (int k = 1; k < 2 * NQ; k++) cs *= cosv[k];
        const float sc2 = cs * cs;
        float r0, r1; upk(r, r0, r1);
        out[(2 * b) * NQ + tid]     = r0 * sc2;
        out[(2 * b + 1) * NQ + tid] = r1 * sc2;
    }
}

extern "C" void kernel_launch(void* const* d_in, const int* in_sizes, int n_in,
                              void* d_out, int out_size)
{
    const float* x  = (const float*)d_in[0];   // (1024, 12) float32
    const float* th = (const float*)d_in[1];   // (2, 12)    float32
    float* o = (float*)d_out;                  // (1024, 12) float32
    (void)in_sizes; (void)n_in; (void)out_size;
    qc_kernel<<<512, THREADS>>>(x, th, o);
}

// round 10
// speedup vs baseline: 1.0058x; 1.0058x over previous
#include <cuda_runtime.h>

#define NQ      12
#define DIM     4096
#define THREADS 256
#define EPT     16
#define STSZ    4352            // max padded addr 4350
#define SMEM_DYN (STSZ * 16)    // ulonglong2 elements
typedef unsigned long long ull;

#define SGN2  0x8000000080000000ULL

__device__ __forceinline__ ull pk(float lo, float hi) {
    ull r; asm("mov.b64 %0, {%1, %2};" : "=l"(r) : "f"(lo), "f"(hi)); return r;
}
__device__ __forceinline__ void upk(ull a, float& lo, float& hi) {
    asm("mov.b64 {%0, %1}, %2;" : "=f"(lo), "=f"(hi) : "l"(a));
}
__device__ __forceinline__ ull fma2(ull a, ull b, ull c) {
    ull d; asm("fma.rn.f32x2 %0, %1, %2, %3;" : "=l"(d) : "l"(a), "l"(b), "l"(c)); return d;
}
__device__ __forceinline__ ull mul2(ull a, ull b) {
    ull d; asm("mul.rn.f32x2 %0, %1, %2;" : "=l"(d) : "l"(a), "l"(b)); return d;
}
__device__ __forceinline__ ull add2(ull a, ull b) {
    ull d; asm("add.rn.f32x2 %0, %1, %2;" : "=l"(d) : "l"(a), "l"(b)); return d;
}
__device__ __forceinline__ ull sub2(ull a, ull b) { return fma2(b, 0xBF800000BF800000ULL, a); }
__device__ __forceinline__ ulonglong2 mk2(ull a, ull b) { ulonglong2 w; w.x = a; w.y = b; return w; }

// dual-state tan-form RY butterfly (deferred cosines)
#define REG_BF4T2(TT, TNT, QBASE)                                          \
    _Pragma("unroll")                                                      \
    for (int rb = 0; rb < 4; rb++) {                                       \
        const ull t2  = (TT)[(QBASE) + rb];                                \
        const ull nt2 = (TNT)[(QBASE) + rb];                               \
        _Pragma("unroll")                                                  \
        for (int m = 0; m < 8; m++) {                                      \
            const int low = (1 << rb) - 1;                                 \
            const int j0  = ((m & ~low) << 1) | (m & low);                 \
            const int j1  = j0 | (1 << rb);                                \
            ull a0 = va[j0];                                               \
            va[j0] = fma2(nt2, va[j1], a0);                                \
            va[j1] = fma2(t2,  a0,   va[j1]);                              \
            ull b0 = vb[j0];                                               \
            vb[j0] = fma2(nt2, vb[j1], b0);                                \
            vb[j1] = fma2(t2,  b0,   vb[j1]);                              \
        }                                                                  \
    }

__device__ __forceinline__ void walsh(const ull* v, ull& P, ull& g1, ull& g3, ull& g7, ull& gF)
{
    ull a[8], d[8];
    #pragma unroll
    for (int k = 0; k < 8; k++) {
        ull pe = mul2(v[2 * k],     v[2 * k]);
        ull po = mul2(v[2 * k + 1], v[2 * k + 1]);
        a[k] = add2(pe, po);
        d[k] = sub2(pe, po);
    }
    P  = add2(add2(add2(a[0], a[1]), add2(a[2], a[3])),
              add2(add2(a[4], a[5]), add2(a[6], a[7])));
    ull e0 = add2(d[0], d[1]), e1 = add2(d[2], d[3]);
    ull e2 = add2(d[4], d[5]), e3 = add2(d[6], d[7]);
    ull f0 = sub2(d[0], d[1]), f1 = sub2(d[2], d[3]);
    ull f2 = sub2(d[4], d[5]), f3 = sub2(d[6], d[7]);
    g1 = add2(add2(e0, e1), add2(e2, e3));
    g3 = add2(add2(f0, f1), add2(f2, f3));
    g7 = add2(sub2(f0, f1), sub2(f2, f3));
    gF = sub2(add2(f0, f3), add2(f1, f2));
}

__global__ __launch_bounds__(THREADS, 2)
void qc_kernel(const float* __restrict__ x,
               const float* __restrict__ th,
               float* __restrict__ out)
{
    extern __shared__ ulonglong2 st4[];          // STSZ elements (dynamic)
    __shared__ float exc[4][NQ], exs[4][NQ];
    __shared__ ull  pca[NQ], psa[NQ], pcb[NQ], psb[NQ];
    __shared__ ull  th_t[2][NQ], th_nt[2][NQ];
    __shared__ float cosv[2 * NQ];
    __shared__ ull  redA[8 * NQ], redB[8 * NQ];

    const int b    = blockIdx.x;                 // batch items 4b .. 4b+3
    const int tid  = threadIdx.x;
    const int lane = tid & 31;

    // padded bases (16B elements; conflict-free A/B/C at LDS.128 granularity)
    const int baseA = 17 * tid;                               // + j
    const int baseB = tid + (tid >> 4);                       // + 272*j
    const int tb    = ((tid >> 5) & 1) | (((tid >> 4) & 1) << 1)
                    | (((tid >> 6) & 1) << 2) | (((tid >> 7) & 1) << 3);
    const int baseC = (tid & 15) + 272 * tb;                  // + 17*j

    // ---- angle precompute ----
    if (tid < 48) {
        int i = tid / NQ, q = tid - NQ * i;      // item i of this CTA, qubit q
        float s_, c_;
        sincosf(0.5f * x[(4 * b + i) * NQ + q], &s_, &c_);
        exc[i][q] = c_; exs[i][q] = s_;
    } else if (tid >= 64 && tid < 64 + 2 * NQ) {
        int k = tid - 64;                        // layer*12 + q
        float s_, c_;
        sincosf(0.5f * th[k], &s_, &c_);
        float t_ = s_ / c_;
        th_t[k / NQ][k % NQ]  = pk(t_, t_);
        th_nt[k / NQ][k % NQ] = pk(-t_, -t_);
        cosv[k] = c_;
    }
    __syncthreads();
    if (tid < NQ) {
        pca[tid] = pk(exc[0][tid], exc[1][tid]);
        psa[tid] = pk(exs[0][tid], exs[1][tid]);
    } else if (tid < 2 * NQ) {
        int q = tid - NQ;
        pcb[q] = pk(exc[2][q], exc[3][q]);
        psb[q] = pk(exs[2][q], exs[3][q]);
    }
    __syncthreads();

    // ---- packed product states (ownership A: s = 16*tid + j) ----
    ull va[EPT], vb[EPT];
    {
        ull ha = (tid & 1) ? psa[4] : pca[4];
        ull hb = (tid & 1) ? psb[4] : pcb[4];
        #pragma unroll
        for (int i = 1; i < 8; i++) {
            int bit = (tid >> i) & 1;
            ha = mul2(ha, bit ? psa[4 + i] : pca[4 + i]);
            hb = mul2(hb, bit ? psb[4 + i] : pcb[4 + i]);
        }
        ull loa[4], hia[4], lob[4], hib[4];
        #pragma unroll
        for (int m = 0; m < 4; m++) {
            loa[m] = mul2((m & 1) ? psa[0] : pca[0], (m & 2) ? psa[1] : pca[1]);
            hia[m] = mul2((m & 1) ? psa[2] : pca[2], (m & 2) ? psa[3] : pca[3]);
            lob[m] = mul2((m & 1) ? psb[0] : pcb[0], (m & 2) ? psb[1] : pcb[1]);
            hib[m] = mul2((m & 1) ? psb[2] : pcb[2], (m & 2) ? psb[3] : pcb[3]);
        }
        #pragma unroll
        for (int j = 0; j < EPT; j++) {
            va[j] = mul2(mul2(ha, loa[j & 3]), hia[j >> 2]);
            vb[j] = mul2(mul2(hb, lob[j & 3]), hib[j >> 2]);
        }
    }

    // ---- variational layers (tan-form gates, cosines deferred) ----
    #pragma unroll
    for (int layer = 0; layer < 2; layer++) {
        const ull* T  = th_t[layer];
        const ull* NT = th_nt[layer];

        REG_BF4T2(T, NT, 0)                      // qubits 0-3 (A)

        #pragma unroll
        for (int j = 0; j < EPT; j++) st4[baseA + j] = mk2(va[j], vb[j]);
        __syncthreads();
        #pragma unroll
        for (int j = 0; j < EPT; j++) {
            ulonglong2 w = st4[baseC + 17 * j];
            va[j] = w.x; vb[j] = w.y;
        }

        REG_BF4T2(T, NT, 4)                      // qubits 4-7 (C)

        #pragma unroll
        for (int j = 0; j < EPT; j++) st4[baseC + 17 * j] = mk2(va[j], vb[j]);
        __syncthreads();
        #pragma unroll
        for (int j = 0; j < EPT; j++) {
            ulonglong2 w = st4[baseB + 272 * j];
            va[j] = w.x; vb[j] = w.y;
        }

        REG_BF4T2(T, NT, 8)                      // qubits 8-11 (B)

        if (layer == 0) {
            // CNOT ring = bit-linear permutation; scatter B -> gather A
            unsigned px = tid; px ^= px << 1; px ^= px << 2; px ^= px << 4;
            const int Pt  = (px >> 7) & 1;
            const int Tt  = (tid ^ (int)(px << 1)) & 0xFE;
            const int t0p = (tid & 1) ^ Pt;
            const int pb0 = Tt + t0p       + (Tt >> 4);
            const int pb1 = Tt + (t0p ^ 1) + (Tt >> 4);
            const int msk = Pt ? 15 : 0;

            __syncthreads();                     // all B reads done before scatter
            #pragma unroll
            for (int j = 0; j < EPT; j++) {
                const int j0 = j & 1, j1 = (j >> 1) & 1, j2 = (j >> 2) & 1, j3 = (j >> 3) & 1;
                const int Jv = j0 | ((j1 ^ j0) << 1) | ((j2 ^ j1 ^ j0) << 2)
                             | ((j3 ^ j2 ^ j1 ^ j0) << 3);
                const int pj = j0 ^ j1 ^ j2 ^ j3;
                st4[(pj ? pb1 : pb0) + 272 * (Jv ^ msk)] = mk2(va[j], vb[j]);
            }
            __syncthreads();
            #pragma unroll
            for (int j = 0; j < EPT; j++) {
                ulonglong2 w = st4[baseA + j];
                va[j] = w.x; vb[j] = w.y;
            }
        }
        // layer 1: ring permutation folded into expectation signs
    }

    // ---- expectations (ownership B) via packed Walsh combine, both states ----
    ull PA, g1A, g3A, g7A, gFA, PB, g1B, g3B, g7B, gFB;
    walsh(va, PA, g1A, g3A, g7A, gFA);
    walsh(vb, PB, g1B, g3B, g7B, gFB);

    const int pt  = __popc(tid) & 1;
    const int pt1 = __popc(tid >> 1) & 1;

    ull accA[NQ], accB[NQ];
    accA[0] = pt1 ? (gFA ^ SGN2) : gFA;
    accB[0] = pt1 ? (gFB ^ SGN2) : gFB;
    #pragma unroll
    for (int q = 1; q < 8; q++) {
        int sq = __popc(tid & ((1 << (q + 1)) - 1)) & 1;
        accA[q] = sq ? (PA ^ SGN2) : PA;
        accB[q] = sq ? (PB ^ SGN2) : PB;
    }
    accA[8]  = pt ? (g1A ^ SGN2) : g1A;   accB[8]  = pt ? (g1B ^ SGN2) : g1B;
    accA[9]  = pt ? (g3A ^ SGN2) : g3A;   accB[9]  = pt ? (g3B ^ SGN2) : g3B;
    accA[10] = pt ? (g7A ^ SGN2) : g7A;   accB[10] = pt ? (g7B ^ SGN2) : g7B;
    accA[11] = pt ? (gFA ^ SGN2) : gFA;   accB[11] = pt ? (gFB ^ SGN2) : gFB;

    #pragma unroll
    for (int q = 0; q < NQ; q++) {
        #pragma unroll
        for (int off = 16; off; off >>= 1) {
            accA[q] = add2(accA[q], __shfl_down_sync(0xFFFFFFFFu, accA[q], off));
            accB[q] = add2(accB[q], __shfl_down_sync(0xFFFFFFFFu, accB[q], off));
        }
    }
    const int w = tid >> 5;
    if (lane == 0) {
        #pragma unroll
        for (int q = 0; q < NQ; q++) {
            redA[w * NQ + q] = accA[q];
            redB[w * NQ + q] = accB[q];
        }
    }
    __syncthreads();
    if (tid < NQ) {
        ull ra = redA[tid], rb = redB[tid];
        #pragma unroll
        for (int w2 = 1; w2 < THREADS / 32; w2++) {
            ra = add2(ra, redA[w2 * NQ + tid]);
            rb = add2(rb, redB[w2 * NQ + tid]);
        }
        // deferred cosine scale: out *= (prod_{24 gates} cos)^2
        float cs = cosv[0];
        #pragma unroll
        for (int k = 1; k < 2 * NQ; k++) cs *= cosv[k];
        const float sc2 = cs * cs;
        float r0, r1, r2, r3;
        upk(ra, r0, r1);
        upk(rb, r2, r3);
        out[(4 * b + 0) * NQ + tid] = r0 * sc2;
        out[(4 * b + 1) * NQ + tid] = r1 * sc2;
        out[(4 * b + 2) * NQ + tid] = r2 * sc2;
        out[(4 * b + 3) * NQ + tid] = r3 * sc2;
    }
}

extern "C" void kernel_launch(void* const* d_in, const int* in_sizes, int n_in,
                              void* d_out, int out_size)
{
    const float* x  = (const float*)d_in[0];   // (1024, 12) float32
    const float* th = (const float*)d_in[1];   // (2, 12)    float32
    float* o = (float*)d_out;                  // (1024, 12) float32
    (void)in_sizes; (void)n_in; (void)out_size;
    cudaFuncSetAttribute(qc_kernel, cudaFuncAttributeMaxDynamicSharedMemorySize, SMEM_DYN);
    qc_kernel<<<256, THREADS, SMEM_DYN>>>(x, th, o);
}